// round 10
// baseline (speedup 1.0000x reference)
#include <cuda_runtime.h>
#include <cuda_bf16.h>
#include <cstdint>

#define N_AG  1024
#define HID   128
#define KDIM  2048
#define OUTD  128
#define CELLS 1024

// ---- scratch (device globals; no allocs allowed) ----
__device__ __align__(16) __nv_bfloat16 g_Ah[N_AG * HID];     // hidden hi
__device__ __align__(16) __nv_bfloat16 g_Al[N_AG * HID];     // hidden lo
__device__ __align__(16) __nv_bfloat16 g_Bh[KDIM * HID];     // Wperm hi
__device__ __align__(16) __nv_bfloat16 g_Bl[KDIM * HID];     // Wperm lo
__device__ float g_P[N_AG * KDIM];             // 8 MB projections
__device__ int   g_ent[N_AG * CELLS];
__device__ int   g_cnt[N_AG];

__device__ __forceinline__ uint32_t smem_u32(const void* p) {
    uint32_t a;
    asm("{ .reg .u64 t; cvta.to.shared.u64 t, %1; cvt.u32.u64 %0, t; }" : "=r"(a) : "l"(p));
    return a;
}
__device__ __forceinline__ void ldsm_x4(uint32_t& r0, uint32_t& r1, uint32_t& r2, uint32_t& r3,
                                        uint32_t addr) {
    asm volatile("ldmatrix.sync.aligned.m8n8.x4.shared.b16 {%0,%1,%2,%3}, [%4];"
                 : "=r"(r0), "=r"(r1), "=r"(r2), "=r"(r3) : "r"(addr));
}
__device__ __forceinline__ void mma16816(float* c, const uint32_t* a, const uint32_t* b) {
    asm volatile("mma.sync.aligned.m16n8k16.row.col.f32.bf16.bf16.f32 "
                 "{%0,%1,%2,%3}, {%4,%5,%6,%7}, {%8,%9}, {%0,%1,%2,%3};"
                 : "+f"(c[0]), "+f"(c[1]), "+f"(c[2]), "+f"(c[3])
                 : "r"(a[0]), "r"(a[1]), "r"(a[2]), "r"(a[3]), "r"(b[0]), "r"(b[1]));
}
__device__ __forceinline__ void cp_async16(uint32_t dst, const void* src) {
    asm volatile("cp.async.cg.shared.global [%0], [%1], 16;" :: "r"(dst), "l"(src) : "memory");
}

// ======================= fused prep kernel (128 thr) =========================
// blocks [0,64): convW | [64,320): convH | [320,1344): scatter (1 ego each)
// 1344 blocks x 128 thr = 172K threads -> single wave.
#define NT 16      // n rows per convW tile
#define KT 256     // k cols per convW tile

struct SmW { float w[NT][KT + 1]; };                        // ~16.1 KB
struct SmS { float2 obs[N_AG]; int w[CELLS]; int cnt; };    // ~12 KB

__global__ void __launch_bounds__(128) prep_kernel(const float* __restrict__ W,
                                                   const float* __restrict__ Hs,
                                                   const float* __restrict__ obs2) {
    __shared__ union { SmW cw; SmS sc; } sm;
    const int b0 = blockIdx.x;
    const int t  = threadIdx.x;   // 128

    if (b0 < 64) {     // ---- convW: staged transpose, coalesced both ways ----
        const int nt = b0 >> 3, kt = b0 & 7;
        const int n0 = nt * NT, k0 = kt * KT, h0 = kt * 16;
        // load 16x256 fp32 tile: float4 LDG, scalar STS (257-stride rows are
        // conflict-free on readout but not 16B aligned -> no STS.128)
#pragma unroll
        for (int q = t; q < NT * KT / 4; q += 128) {   // 1024 float4s
            int r = q >> 6, c4 = q & 63;
            float4 v = *(const float4*)(W + (n0 + r) * KDIM + k0 + c4 * 4);
            sm.cw.w[r][c4 * 4 + 0] = v.x;
            sm.cw.w[r][c4 * 4 + 1] = v.y;
            sm.cw.w[r][c4 * 4 + 2] = v.z;
            sm.cw.w[r][c4 * 4 + 3] = v.w;
        }
        __syncthreads();
        // write: 256 (blk,nn) rows, 2 per thread; 16 h values each (32B runs)
#pragma unroll
        for (int p = t; p < 256; p += 128) {
            const int blk = p >> 4, nn = p & 15;
            const int r = (blk << 7) | (n0 + nn);
            __align__(16) __nv_bfloat16 hi[16];
            __align__(16) __nv_bfloat16 lo[16];
#pragma unroll
            for (int hr = 0; hr < 16; hr++) {
                float v = sm.cw.w[nn][hr * 16 + blk];
                hi[hr] = __float2bfloat16(v);
                lo[hr] = __float2bfloat16(v - __bfloat162float(hi[hr]));
            }
            *(uint4*)(g_Bh + r * HID + h0)     = *(const uint4*)&hi[0];
            *(uint4*)(g_Bh + r * HID + h0 + 8) = *(const uint4*)&hi[8];
            *(uint4*)(g_Bl + r * HID + h0)     = *(const uint4*)&lo[0];
            *(uint4*)(g_Bl + r * HID + h0 + 8) = *(const uint4*)&lo[8];
        }
        return;
    }
    if (b0 < 320) {    // ---- convH: float4 vectorized bf16 split ----
        int q = (b0 - 64) * 128 + t;                  // 32768 float4s
        float4 v = ((const float4*)Hs)[q];
        __align__(8) __nv_bfloat16 hi[4];
        __align__(8) __nv_bfloat16 lo[4];
        hi[0] = __float2bfloat16(v.x); lo[0] = __float2bfloat16(v.x - __bfloat162float(hi[0]));
        hi[1] = __float2bfloat16(v.y); lo[1] = __float2bfloat16(v.y - __bfloat162float(hi[1]));
        hi[2] = __float2bfloat16(v.z); lo[2] = __float2bfloat16(v.z - __bfloat162float(hi[2]));
        hi[3] = __float2bfloat16(v.w); lo[3] = __float2bfloat16(v.w - __bfloat162float(hi[3]));
        *(uint2*)(g_Ah + q * 4) = *(const uint2*)&hi[0];
        *(uint2*)(g_Al + q * 4) = *(const uint2*)&lo[0];
        return;
    }

    // ---- scatter: 1 ego per CTA, set-semantics (max j wins) ----
    const int i = b0 - 320;
    for (int j = t; j < N_AG; j += 128) sm.sc.obs[j] = ((const float2*)obs2)[j];
    for (int c = t; c < CELLS; c += 128) sm.sc.w[c] = -1;
    if (t == 0) sm.sc.cnt = 0;
    __syncthreads();

    const float xi = sm.sc.obs[i].x, yi = sm.sc.obs[i].y;
    if (xi != xi) {                                  // ego NaN
        if (t == 0) g_cnt[i] = 0;
        return;
    }
    for (int j = t; j < N_AG; j += 128) {
        if (j == i) continue;
        float xj = sm.sc.obs[j].x, yj = sm.sc.obs[j].y;
        if (xj != xj) continue;
        float ox = (xj - xi) * 4.0f + 16.0f;         // exact pow2 scale
        float oy = (yj - yi) * 4.0f + 16.0f;
        if (ox >= 0.0f && ox < 32.0f && oy >= 0.0f && oy < 32.0f)
            atomicMax(&sm.sc.w[((int)ox) * 32 + (int)oy], j);
    }
    __syncthreads();

    int* ent = g_ent + (i << 10);
    for (int c = t; c < CELLS; c += 128) {
        int j = sm.sc.w[c];
        if (j >= 0) {
            int blk = ((c >> 8) << 2) | ((c & 31) >> 3);
            int p = atomicAdd(&sm.sc.cnt, 1);
            ent[p] = (j << 11) | (blk << 7);         // offset into P
        }
    }
    __syncthreads();
    if (t == 0) g_cnt[i] = sm.sc.cnt;
}

// ============================ mma.sync GEMM ==================================
// P = hidden(1024x128) @ Wperm^T(2048x128). grid(8,16), 256 thr, 128x128 tile.
// 3 bf16 passes (Ah*Bh + Ah*Bl + Al*Bh), fragments loaded ONCE per k-step.
#define LDS   136
#define TILE  (128 * LDS)
#define SMEM_DYN (4 * TILE * 2)            // 139264 B

__device__ __forceinline__ void load_tile_async(__nv_bfloat16* dst,
                                                const __nv_bfloat16* src, int row0) {
    const int t = threadIdx.x;             // 256
#pragma unroll
    for (int q = t; q < 2048; q += 256) {  // 16B chunks
        int r = q >> 4, c = q & 15;
        cp_async16(smem_u32(dst + r * LDS + c * 8), src + (row0 + r) * HID + c * 8);
    }
}

__global__ void __launch_bounds__(256, 1) gemm_mma_kernel() {
    extern __shared__ __nv_bfloat16 sm[];
    __nv_bfloat16* sAh = sm;
    __nv_bfloat16* sAl = sm + TILE;
    __nv_bfloat16* sBh = sm + 2 * TILE;
    __nv_bfloat16* sBl = sm + 3 * TILE;

    const int t  = threadIdx.x;
    const int w  = t >> 5;
    const int l  = t & 31;
    const int m0 = blockIdx.x << 7;
    const int n0 = blockIdx.y << 7;
    const int wm = (w >> 2) * 64;
    const int wn = (w & 3) * 32;

    load_tile_async(sAh, g_Ah, m0);
    load_tile_async(sAl, g_Al, m0);
    load_tile_async(sBh, g_Bh, n0);
    load_tile_async(sBl, g_Bl, n0);
    asm volatile("cp.async.commit_group;" ::: "memory");
    asm volatile("cp.async.wait_group 0;" ::: "memory");
    __syncthreads();

    float acc[4][4][4];
#pragma unroll
    for (int mi = 0; mi < 4; mi++)
#pragma unroll
        for (int ni = 0; ni < 4; ni++)
#pragma unroll
            for (int q = 0; q < 4; q++) acc[mi][ni][q] = 0.0f;

    const int aRow = wm + (l & 15);
    const int aCol = (l >> 4) * 8;
    const int bRow = wn + ((l >> 4) * 8) + (l & 7);
    const int bCol = ((l >> 3) & 1) * 8;

    const uint32_t aHB = smem_u32(sAh + aRow * LDS + aCol);
    const uint32_t aLB = smem_u32(sAl + aRow * LDS + aCol);
    const uint32_t bHB = smem_u32(sBh + bRow * LDS + bCol);
    const uint32_t bLB = smem_u32(sBl + bRow * LDS + bCol);

#pragma unroll
    for (int kk = 0; kk < 8; kk++) {
        const uint32_t ko = kk * 32;       // kk*16 elements * 2B
        uint32_t aH[4][4], aL[4][4], bH[4][2], bL[4][2];
#pragma unroll
        for (int mi = 0; mi < 4; mi++) {
            ldsm_x4(aH[mi][0], aH[mi][1], aH[mi][2], aH[mi][3],
                    aHB + mi * (16 * LDS * 2) + ko);
            ldsm_x4(aL[mi][0], aL[mi][1], aL[mi][2], aL[mi][3],
                    aLB + mi * (16 * LDS * 2) + ko);
        }
#pragma unroll
        for (int bi = 0; bi < 2; bi++) {
            ldsm_x4(bH[2 * bi][0], bH[2 * bi][1], bH[2 * bi + 1][0], bH[2 * bi + 1][1],
                    bHB + bi * (16 * LDS * 2) + ko);
            ldsm_x4(bL[2 * bi][0], bL[2 * bi][1], bL[2 * bi + 1][0], bL[2 * bi + 1][1],
                    bLB + bi * (16 * LDS * 2) + ko);
        }
#pragma unroll
        for (int mi = 0; mi < 4; mi++)
#pragma unroll
            for (int ni = 0; ni < 4; ni++) {
                mma16816(acc[mi][ni], aH[mi], bH[ni]);
                mma16816(acc[mi][ni], aH[mi], bL[ni]);
                mma16816(acc[mi][ni], aL[mi], bH[ni]);
            }
    }

    const int g2 = l >> 2, tig = l & 3;
#pragma unroll
    for (int mi = 0; mi < 4; mi++) {
        const int row = m0 + wm + mi * 16 + g2;
#pragma unroll
        for (int ni = 0; ni < 4; ni++) {
            const int col = n0 + wn + ni * 8 + tig * 2;
            *(float2*)(g_P + row * KDIM + col)       = make_float2(acc[mi][ni][0], acc[mi][ni][1]);
            *(float2*)(g_P + (row + 8) * KDIM + col) = make_float2(acc[mi][ni][2], acc[mi][ni][3]);
        }
    }
}

// ============================ output gather =================================
__global__ void out_kernel(const float* __restrict__ b, float* __restrict__ out) {
    __shared__ int    se[CELLS];
    __shared__ float4 sp[8][32];
    const int i = blockIdx.x;
    const int t = threadIdx.x;     // 256
    const int g = t >> 5, l = t & 31;

    const int cnt = g_cnt[i];
    const int* ent = g_ent + (i << 10);
    for (int e = t; e < cnt; e += 256) se[e] = ent[e];
    __syncthreads();

    float4 acc = make_float4(0.f, 0.f, 0.f, 0.f);
    for (int e = g; e < cnt; e += 8) {
        float4 v = *(const float4*)(g_P + se[e] + l * 4);
        acc.x += v.x; acc.y += v.y; acc.z += v.z; acc.w += v.w;
    }
    sp[g][l] = acc;
    __syncthreads();

    if (g == 0) {
        float4 s = sp[0][l];
#pragma unroll
        for (int q = 1; q < 8; q++) {
            float4 v = sp[q][l];
            s.x += v.x; s.y += v.y; s.z += v.z; s.w += v.w;
        }
        float4 bv = ((const float4*)b)[l];
        s.x = fmaxf(s.x + bv.x, 0.f);
        s.y = fmaxf(s.y + bv.y, 0.f);
        s.z = fmaxf(s.z + bv.z, 0.f);
        s.w = fmaxf(s.w + bv.w, 0.f);
        ((float4*)(out + i * OUTD))[l] = s;
    }
}

// =============================================================================
extern "C" void kernel_launch(void* const* d_in, const int* in_sizes, int n_in,
                              void* d_out, int out_size) {
    const float* hidden = (const float*)d_in[0];
    const float* obs2   = (const float*)d_in[2];
    const float* W      = (const float*)d_in[3];
    const float* b      = (const float*)d_in[4];
    float*       out    = (float*)d_out;

    cudaFuncSetAttribute(gemm_mma_kernel, cudaFuncAttributeMaxDynamicSharedMemorySize, SMEM_DYN);

    prep_kernel<<<1344, 128>>>(W, hidden, obs2);
    dim3 ggrid(N_AG / 128, KDIM / 128);   // (8, 16)
    gemm_mma_kernel<<<ggrid, 256, SMEM_DYN>>>();
    out_kernel<<<N_AG, 256>>>(b, out);
}

// round 11
// speedup vs baseline: 1.0917x; 1.0917x over previous
#include <cuda_runtime.h>
#include <cuda_bf16.h>
#include <cstdint>

#define N_AG  1024
#define HID   128
#define KDIM  2048
#define OUTD  128
#define CELLS 1024

// ---- scratch (device globals; no allocs allowed) ----
__device__ __align__(16) __nv_bfloat16 g_Ah[N_AG * HID];     // hidden hi
__device__ __align__(16) __nv_bfloat16 g_Al[N_AG * HID];     // hidden lo
__device__ __align__(16) __nv_bfloat16 g_Bh[KDIM * HID];     // Wperm hi
__device__ __align__(16) __nv_bfloat16 g_Bl[KDIM * HID];     // Wperm lo
__device__ float g_P[N_AG * KDIM];             // 8 MB projections

__device__ __forceinline__ uint32_t smem_u32(const void* p) {
    uint32_t a;
    asm("{ .reg .u64 t; cvta.to.shared.u64 t, %1; cvt.u32.u64 %0, t; }" : "=r"(a) : "l"(p));
    return a;
}
__device__ __forceinline__ void ldsm_x4(uint32_t& r0, uint32_t& r1, uint32_t& r2, uint32_t& r3,
                                        uint32_t addr) {
    asm volatile("ldmatrix.sync.aligned.m8n8.x4.shared.b16 {%0,%1,%2,%3}, [%4];"
                 : "=r"(r0), "=r"(r1), "=r"(r2), "=r"(r3) : "r"(addr));
}
__device__ __forceinline__ void mma16816(float* c, const uint32_t* a, const uint32_t* b) {
    asm volatile("mma.sync.aligned.m16n8k16.row.col.f32.bf16.bf16.f32 "
                 "{%0,%1,%2,%3}, {%4,%5,%6,%7}, {%8,%9}, {%0,%1,%2,%3};"
                 : "+f"(c[0]), "+f"(c[1]), "+f"(c[2]), "+f"(c[3])
                 : "r"(a[0]), "r"(a[1]), "r"(a[2]), "r"(a[3]), "r"(b[0]), "r"(b[1]));
}
__device__ __forceinline__ void cp_async16(uint32_t dst, const void* src) {
    asm volatile("cp.async.cg.shared.global [%0], [%1], 16;" :: "r"(dst), "l"(src) : "memory");
}

// ======================= prep kernel (convs only, 256 thr) ===================
// blocks [0,64): convW tiled transpose | [64,192): convH
#define NT 16      // n rows per convW tile
#define KT 256     // k cols per convW tile

__global__ void __launch_bounds__(256) prep_kernel(const float* __restrict__ W,
                                                   const float* __restrict__ Hs) {
    __shared__ float cw[NT][KT + 1];     // ~16.1 KB
    const int b0 = blockIdx.x;
    const int t  = threadIdx.x;   // 256

    if (b0 < 64) {     // ---- convW: staged transpose, coalesced both ways ----
        const int nt = b0 >> 3, kt = b0 & 7;
        const int n0 = nt * NT, k0 = kt * KT, h0 = kt * 16;
        // load 16x256 fp32 tile: float4 LDG, scalar STS (257-stride rows are
        // conflict-free on readout but not 16B aligned -> no STS.128)
#pragma unroll
        for (int q = t; q < NT * KT / 4; q += 256) {   // 1024 float4s
            int r = q >> 6, c4 = q & 63;
            float4 v = *(const float4*)(W + (n0 + r) * KDIM + k0 + c4 * 4);
            cw[r][c4 * 4 + 0] = v.x;
            cw[r][c4 * 4 + 1] = v.y;
            cw[r][c4 * 4 + 2] = v.z;
            cw[r][c4 * 4 + 3] = v.w;
        }
        __syncthreads();
        // write: 256 (blk,nn) rows, 1 per thread; 16 h values each (32B runs)
        {
            const int blk = t >> 4, nn = t & 15;
            const int r = (blk << 7) | (n0 + nn);
            __align__(16) __nv_bfloat16 hi[16];
            __align__(16) __nv_bfloat16 lo[16];
#pragma unroll
            for (int hr = 0; hr < 16; hr++) {
                float v = cw[nn][hr * 16 + blk];
                hi[hr] = __float2bfloat16(v);
                lo[hr] = __float2bfloat16(v - __bfloat162float(hi[hr]));
            }
            *(uint4*)(g_Bh + r * HID + h0)     = *(const uint4*)&hi[0];
            *(uint4*)(g_Bh + r * HID + h0 + 8) = *(const uint4*)&hi[8];
            *(uint4*)(g_Bl + r * HID + h0)     = *(const uint4*)&lo[0];
            *(uint4*)(g_Bl + r * HID + h0 + 8) = *(const uint4*)&lo[8];
        }
        return;
    }
    // ---- convH: float4 vectorized bf16 split ----
    int q = (b0 - 64) * 256 + t;                  // 32768 float4s
    float4 v = ((const float4*)Hs)[q];
    __align__(8) __nv_bfloat16 hi[4];
    __align__(8) __nv_bfloat16 lo[4];
    hi[0] = __float2bfloat16(v.x); lo[0] = __float2bfloat16(v.x - __bfloat162float(hi[0]));
    hi[1] = __float2bfloat16(v.y); lo[1] = __float2bfloat16(v.y - __bfloat162float(hi[1]));
    hi[2] = __float2bfloat16(v.z); lo[2] = __float2bfloat16(v.z - __bfloat162float(hi[2]));
    hi[3] = __float2bfloat16(v.w); lo[3] = __float2bfloat16(v.w - __bfloat162float(hi[3]));
    *(uint2*)(g_Ah + q * 4) = *(const uint2*)&hi[0];
    *(uint2*)(g_Al + q * 4) = *(const uint2*)&lo[0];
}

// ============================ mma.sync GEMM ==================================
// P = hidden(1024x128) @ Wperm^T(2048x128). grid(8,16), 256 thr, 128x128 tile.
// 3 bf16 passes (Ah*Bh + Ah*Bl + Al*Bh), fragments loaded ONCE per k-step.
#define LDS   136
#define TILE  (128 * LDS)
#define SMEM_DYN (4 * TILE * 2)            // 139264 B

__device__ __forceinline__ void load_tile_async(__nv_bfloat16* dst,
                                                const __nv_bfloat16* src, int row0) {
    const int t = threadIdx.x;             // 256
#pragma unroll
    for (int q = t; q < 2048; q += 256) {  // 16B chunks
        int r = q >> 4, c = q & 15;
        cp_async16(smem_u32(dst + r * LDS + c * 8), src + (row0 + r) * HID + c * 8);
    }
}

__global__ void __launch_bounds__(256, 1) gemm_mma_kernel() {
    extern __shared__ __nv_bfloat16 sm[];
    __nv_bfloat16* sAh = sm;
    __nv_bfloat16* sAl = sm + TILE;
    __nv_bfloat16* sBh = sm + 2 * TILE;
    __nv_bfloat16* sBl = sm + 3 * TILE;

    const int t  = threadIdx.x;
    const int w  = t >> 5;
    const int l  = t & 31;
    const int m0 = blockIdx.x << 7;
    const int n0 = blockIdx.y << 7;
    const int wm = (w >> 2) * 64;
    const int wn = (w & 3) * 32;

    load_tile_async(sAh, g_Ah, m0);
    load_tile_async(sAl, g_Al, m0);
    load_tile_async(sBh, g_Bh, n0);
    load_tile_async(sBl, g_Bl, n0);
    asm volatile("cp.async.commit_group;" ::: "memory");
    asm volatile("cp.async.wait_group 0;" ::: "memory");
    __syncthreads();

    float acc[4][4][4];
#pragma unroll
    for (int mi = 0; mi < 4; mi++)
#pragma unroll
        for (int ni = 0; ni < 4; ni++)
#pragma unroll
            for (int q = 0; q < 4; q++) acc[mi][ni][q] = 0.0f;

    const int aRow = wm + (l & 15);
    const int aCol = (l >> 4) * 8;
    const int bRow = wn + ((l >> 4) * 8) + (l & 7);
    const int bCol = ((l >> 3) & 1) * 8;

    const uint32_t aHB = smem_u32(sAh + aRow * LDS + aCol);
    const uint32_t aLB = smem_u32(sAl + aRow * LDS + aCol);
    const uint32_t bHB = smem_u32(sBh + bRow * LDS + bCol);
    const uint32_t bLB = smem_u32(sBl + bRow * LDS + bCol);

#pragma unroll
    for (int kk = 0; kk < 8; kk++) {
        const uint32_t ko = kk * 32;       // kk*16 elements * 2B
        uint32_t aH[4][4], aL[4][4], bH[4][2], bL[4][2];
#pragma unroll
        for (int mi = 0; mi < 4; mi++) {
            ldsm_x4(aH[mi][0], aH[mi][1], aH[mi][2], aH[mi][3],
                    aHB + mi * (16 * LDS * 2) + ko);
            ldsm_x4(aL[mi][0], aL[mi][1], aL[mi][2], aL[mi][3],
                    aLB + mi * (16 * LDS * 2) + ko);
        }
#pragma unroll
        for (int bi = 0; bi < 2; bi++) {
            ldsm_x4(bH[2 * bi][0], bH[2 * bi][1], bH[2 * bi + 1][0], bH[2 * bi + 1][1],
                    bHB + bi * (16 * LDS * 2) + ko);
            ldsm_x4(bL[2 * bi][0], bL[2 * bi][1], bL[2 * bi + 1][0], bL[2 * bi + 1][1],
                    bLB + bi * (16 * LDS * 2) + ko);
        }
#pragma unroll
        for (int mi = 0; mi < 4; mi++)
#pragma unroll
            for (int ni = 0; ni < 4; ni++) {
                mma16816(acc[mi][ni], aH[mi], bH[ni]);
                mma16816(acc[mi][ni], aH[mi], bL[ni]);
                mma16816(acc[mi][ni], aL[mi], bH[ni]);
            }
    }

    const int g2 = l >> 2, tig = l & 3;
#pragma unroll
    for (int mi = 0; mi < 4; mi++) {
        const int row = m0 + wm + mi * 16 + g2;
#pragma unroll
        for (int ni = 0; ni < 4; ni++) {
            const int col = n0 + wn + ni * 8 + tig * 2;
            *(float2*)(g_P + row * KDIM + col)       = make_float2(acc[mi][ni][0], acc[mi][ni][1]);
            *(float2*)(g_P + (row + 8) * KDIM + col) = make_float2(acc[mi][ni][2], acc[mi][ni][3]);
        }
    }
}

// ================= fused scatter + output gather =============================
// One CTA per ego: scatter winner grid in smem (set-semantics: max j wins,
// matching XLA update order), compact, then gather precomputed P rows.
__global__ void __launch_bounds__(256) out_kernel(const float* __restrict__ obs2,
                                                  const float* __restrict__ b,
                                                  float* __restrict__ out) {
    __shared__ int    w[CELLS];
    __shared__ int    se[CELLS];
    __shared__ int    s_cnt;
    __shared__ float4 sp[8][32];
    const int i = blockIdx.x;
    const int t = threadIdx.x;     // 256
    const int g = t >> 5, l = t & 31;

    for (int c = t; c < CELLS; c += 256) w[c] = -1;
    if (t == 0) s_cnt = 0;
    const float2 oi = ((const float2*)obs2)[i];    // broadcast load
    __syncthreads();

    int cnt = 0;
    if (oi.x == oi.x) {                            // ego not NaN
        for (int j = t; j < N_AG; j += 256) {      // obs2 is L2-resident (8KB)
            if (j == i) continue;
            float2 oj = ((const float2*)obs2)[j];
            if (oj.x != oj.x) continue;            // neighbor NaN
            float ox = (oj.x - oi.x) * 4.0f + 16.0f;   // exact pow2 scale
            float oy = (oj.y - oi.y) * 4.0f + 16.0f;
            if (ox >= 0.0f && ox < 32.0f && oy >= 0.0f && oy < 32.0f)
                atomicMax(&w[((int)ox) * 32 + (int)oy], j);
        }
        __syncthreads();
        for (int c = t; c < CELLS; c += 256) {
            int j = w[c];
            if (j >= 0) {
                int blk = ((c >> 8) << 2) | ((c & 31) >> 3);   // gi*4+gj
                int p = atomicAdd(&s_cnt, 1);
                se[p] = (j << 11) | (blk << 7);    // row offset into P
            }
        }
        __syncthreads();
        cnt = s_cnt;
    }

    float4 acc = make_float4(0.f, 0.f, 0.f, 0.f);
    for (int e = g; e < cnt; e += 8) {
        float4 v = *(const float4*)(g_P + se[e] + l * 4);
        acc.x += v.x; acc.y += v.y; acc.z += v.z; acc.w += v.w;
    }
    sp[g][l] = acc;
    __syncthreads();

    if (g == 0) {
        float4 s = sp[0][l];
#pragma unroll
        for (int q = 1; q < 8; q++) {
            float4 v = sp[q][l];
            s.x += v.x; s.y += v.y; s.z += v.z; s.w += v.w;
        }
        float4 bv = ((const float4*)b)[l];
        s.x = fmaxf(s.x + bv.x, 0.f);
        s.y = fmaxf(s.y + bv.y, 0.f);
        s.z = fmaxf(s.z + bv.z, 0.f);
        s.w = fmaxf(s.w + bv.w, 0.f);
        ((float4*)(out + i * OUTD))[l] = s;
    }
}

// =============================================================================
extern "C" void kernel_launch(void* const* d_in, const int* in_sizes, int n_in,
                              void* d_out, int out_size) {
    const float* hidden = (const float*)d_in[0];
    const float* obs2   = (const float*)d_in[2];
    const float* W      = (const float*)d_in[3];
    const float* b      = (const float*)d_in[4];
    float*       out    = (float*)d_out;

    cudaFuncSetAttribute(gemm_mma_kernel, cudaFuncAttributeMaxDynamicSharedMemorySize, SMEM_DYN);

    prep_kernel<<<192, 256>>>(W, hidden);
    dim3 ggrid(N_AG / 128, KDIM / 128);   // (8, 16)
    gemm_mma_kernel<<<ggrid, 256, SMEM_DYN>>>();
    out_kernel<<<N_AG, 256>>>(obs2, b, out);
}

// round 12
// speedup vs baseline: 1.2405x; 1.1364x over previous
#include <cuda_runtime.h>
#include <cuda_bf16.h>
#include <cstdint>

#define N_AG  1024
#define HID   128
#define KDIM  2048
#define OUTD  128
#define CELLS 1024

// ---- scratch (device globals; no allocs allowed) ----
__device__ __align__(16) __nv_bfloat16 g_Bh[KDIM * HID];     // Wperm hi
__device__ __align__(16) __nv_bfloat16 g_Bl[KDIM * HID];     // Wperm lo
__device__ float g_P[N_AG * KDIM];             // 8 MB projections

__device__ __forceinline__ uint32_t smem_u32(const void* p) {
    uint32_t a;
    asm("{ .reg .u64 t; cvta.to.shared.u64 t, %1; cvt.u32.u64 %0, t; }" : "=r"(a) : "l"(p));
    return a;
}
__device__ __forceinline__ void griddep_wait() {
    asm volatile("griddepcontrol.wait;" ::: "memory");
}
__device__ __forceinline__ void griddep_launch() {
    asm volatile("griddepcontrol.launch_dependents;" ::: "memory");
}
__device__ __forceinline__ void ldsm_x4(uint32_t& r0, uint32_t& r1, uint32_t& r2, uint32_t& r3,
                                        uint32_t addr) {
    asm volatile("ldmatrix.sync.aligned.m8n8.x4.shared.b16 {%0,%1,%2,%3}, [%4];"
                 : "=r"(r0), "=r"(r1), "=r"(r2), "=r"(r3) : "r"(addr));
}
__device__ __forceinline__ void mma16816(float* c, const uint32_t* a, const uint32_t* b) {
    asm volatile("mma.sync.aligned.m16n8k16.row.col.f32.bf16.bf16.f32 "
                 "{%0,%1,%2,%3}, {%4,%5,%6,%7}, {%8,%9}, {%0,%1,%2,%3};"
                 : "+f"(c[0]), "+f"(c[1]), "+f"(c[2]), "+f"(c[3])
                 : "r"(a[0]), "r"(a[1]), "r"(a[2]), "r"(a[3]), "r"(b[0]), "r"(b[1]));
}
__device__ __forceinline__ void cp_async16(uint32_t dst, const void* src) {
    asm volatile("cp.async.cg.shared.global [%0], [%1], 16;" :: "r"(dst), "l"(src) : "memory");
}

// ======================= prep kernel: convW only =============================
// 128 blocks: tiled transpose W[n][h*16+blk] -> Wperm[blk*128+n][h], bf16 split.
#define NT 8       // n rows per tile
#define KT 256     // k cols per tile

__global__ void __launch_bounds__(256) prep_kernel(const float* __restrict__ W) {
    __shared__ float cw[NT][KT + 1];     // ~8.1 KB
    const int b0 = blockIdx.x;
    const int t  = threadIdx.x;   // 256

    griddep_launch();             // let gemm start its A-convert immediately

    const int nt = b0 >> 3, kt = b0 & 7;
    const int n0 = nt * NT, k0 = kt * KT, h0 = kt * 16;
    // load 8x256 fp32 tile: float4 LDG, scalar STS (257-stride rows are
    // conflict-free on readout but not 16B aligned -> no STS.128)
#pragma unroll
    for (int q = t; q < NT * KT / 4; q += 256) {   // 512 float4s, 2/thread
        int r = q >> 6, c4 = q & 63;
        float4 v = *(const float4*)(W + (n0 + r) * KDIM + k0 + c4 * 4);
        cw[r][c4 * 4 + 0] = v.x;
        cw[r][c4 * 4 + 1] = v.y;
        cw[r][c4 * 4 + 2] = v.z;
        cw[r][c4 * 4 + 3] = v.w;
    }
    __syncthreads();
    // write: 128 (blk,nn) rows, threads 0..127; 16 h values each (32B runs)
    if (t < 128) {
        const int blk = t >> 3, nn = t & 7;
        const int r = (blk << 7) | (n0 + nn);
        __align__(16) __nv_bfloat16 hi[16];
        __align__(16) __nv_bfloat16 lo[16];
#pragma unroll
        for (int hr = 0; hr < 16; hr++) {
            float v = cw[nn][hr * 16 + blk];
            hi[hr] = __float2bfloat16(v);
            lo[hr] = __float2bfloat16(v - __bfloat162float(hi[hr]));
        }
        *(uint4*)(g_Bh + r * HID + h0)     = *(const uint4*)&hi[0];
        *(uint4*)(g_Bh + r * HID + h0 + 8) = *(const uint4*)&hi[8];
        *(uint4*)(g_Bl + r * HID + h0)     = *(const uint4*)&lo[0];
        *(uint4*)(g_Bl + r * HID + h0 + 8) = *(const uint4*)&lo[8];
    }
}

// ============================ mma.sync GEMM ==================================
// P = hidden(1024x128) @ Wperm^T(2048x128). grid(8,16), 256 thr, 128x128 tile.
// A tile converted fp32->bf16 hi/lo IN-KERNEL (no prep dependency); B tiles
// cp.async'd after griddepcontrol.wait on prep.
#define LDS   136
#define TILE  (128 * LDS)
#define SMEM_DYN (4 * TILE * 2)            // 139264 B

__global__ void __launch_bounds__(256, 1) gemm_mma_kernel(const float* __restrict__ Hs) {
    extern __shared__ __nv_bfloat16 sm[];
    __nv_bfloat16* sAh = sm;
    __nv_bfloat16* sAl = sm + TILE;
    __nv_bfloat16* sBh = sm + 2 * TILE;
    __nv_bfloat16* sBl = sm + 3 * TILE;

    const int t  = threadIdx.x;
    const int w  = t >> 5;
    const int l  = t & 31;
    const int m0 = blockIdx.x << 7;
    const int n0 = blockIdx.y << 7;
    const int wm = (w >> 2) * 64;
    const int wn = (w & 3) * 32;

    // ---- A convert: hidden fp32 -> bf16 hi/lo in smem (no dependency) ----
#pragma unroll
    for (int q = t; q < 4096; q += 256) {  // 128 rows x 32 float4
        int r = q >> 5, c = q & 31;
        float4 v = *(const float4*)(Hs + (m0 + r) * HID + c * 4);
        __align__(8) __nv_bfloat16 hi[4];
        __align__(8) __nv_bfloat16 lo[4];
        hi[0] = __float2bfloat16(v.x); lo[0] = __float2bfloat16(v.x - __bfloat162float(hi[0]));
        hi[1] = __float2bfloat16(v.y); lo[1] = __float2bfloat16(v.y - __bfloat162float(hi[1]));
        hi[2] = __float2bfloat16(v.z); lo[2] = __float2bfloat16(v.z - __bfloat162float(hi[2]));
        hi[3] = __float2bfloat16(v.w); lo[3] = __float2bfloat16(v.w - __bfloat162float(hi[3]));
        *(uint2*)(sAh + r * LDS + c * 4) = *(const uint2*)&hi[0];
        *(uint2*)(sAl + r * LDS + c * 4) = *(const uint2*)&lo[0];
    }

    griddep_launch();             // let out_kernel start its scatter
    griddep_wait();               // g_Bh/g_Bl now visible (prep done)

    // ---- B tiles from prep output ----
#pragma unroll
    for (int q = t; q < 2048; q += 256) {  // 16B chunks
        int r = q >> 4, c = q & 15;
        cp_async16(smem_u32(sBh + r * LDS + c * 8), g_Bh + (n0 + r) * HID + c * 8);
        cp_async16(smem_u32(sBl + r * LDS + c * 8), g_Bl + (n0 + r) * HID + c * 8);
    }
    asm volatile("cp.async.commit_group;" ::: "memory");
    asm volatile("cp.async.wait_group 0;" ::: "memory");
    __syncthreads();

    float acc[4][4][4];
#pragma unroll
    for (int mi = 0; mi < 4; mi++)
#pragma unroll
        for (int ni = 0; ni < 4; ni++)
#pragma unroll
            for (int q = 0; q < 4; q++) acc[mi][ni][q] = 0.0f;

    const int aRow = wm + (l & 15);
    const int aCol = (l >> 4) * 8;
    const int bRow = wn + ((l >> 4) * 8) + (l & 7);
    const int bCol = ((l >> 3) & 1) * 8;

    const uint32_t aHB = smem_u32(sAh + aRow * LDS + aCol);
    const uint32_t aLB = smem_u32(sAl + aRow * LDS + aCol);
    const uint32_t bHB = smem_u32(sBh + bRow * LDS + bCol);
    const uint32_t bLB = smem_u32(sBl + bRow * LDS + bCol);

#pragma unroll
    for (int kk = 0; kk < 8; kk++) {
        const uint32_t ko = kk * 32;       // kk*16 elements * 2B
        uint32_t aH[4][4], aL[4][4], bH[4][2], bL[4][2];
#pragma unroll
        for (int mi = 0; mi < 4; mi++) {
            ldsm_x4(aH[mi][0], aH[mi][1], aH[mi][2], aH[mi][3],
                    aHB + mi * (16 * LDS * 2) + ko);
            ldsm_x4(aL[mi][0], aL[mi][1], aL[mi][2], aL[mi][3],
                    aLB + mi * (16 * LDS * 2) + ko);
        }
#pragma unroll
        for (int bi = 0; bi < 2; bi++) {
            ldsm_x4(bH[2 * bi][0], bH[2 * bi][1], bH[2 * bi + 1][0], bH[2 * bi + 1][1],
                    bHB + bi * (16 * LDS * 2) + ko);
            ldsm_x4(bL[2 * bi][0], bL[2 * bi][1], bL[2 * bi + 1][0], bL[2 * bi + 1][1],
                    bLB + bi * (16 * LDS * 2) + ko);
        }
#pragma unroll
        for (int mi = 0; mi < 4; mi++)
#pragma unroll
            for (int ni = 0; ni < 4; ni++) {
                mma16816(acc[mi][ni], aH[mi], bH[ni]);
                mma16816(acc[mi][ni], aH[mi], bL[ni]);
                mma16816(acc[mi][ni], aL[mi], bH[ni]);
            }
    }

    const int g2 = l >> 2, tig = l & 3;
#pragma unroll
    for (int mi = 0; mi < 4; mi++) {
        const int row = m0 + wm + mi * 16 + g2;
#pragma unroll
        for (int ni = 0; ni < 4; ni++) {
            const int col = n0 + wn + ni * 8 + tig * 2;
            *(float2*)(g_P + row * KDIM + col)       = make_float2(acc[mi][ni][0], acc[mi][ni][1]);
            *(float2*)(g_P + (row + 8) * KDIM + col) = make_float2(acc[mi][ni][2], acc[mi][ni][3]);
        }
    }
}

// ================= fused scatter + output gather =============================
// One CTA per ego. Scatter (obs2 only, runs concurrently with GEMM thanks to
// PDL), then griddepcontrol.wait, then gather precomputed P rows.
__global__ void __launch_bounds__(256) out_kernel(const float* __restrict__ obs2,
                                                  const float* __restrict__ b,
                                                  float* __restrict__ out) {
    __shared__ int    w[CELLS];
    __shared__ int    se[CELLS];
    __shared__ int    s_cnt;
    __shared__ float4 sp[8][32];
    const int i = blockIdx.x;
    const int t = threadIdx.x;     // 256
    const int g = t >> 5, l = t & 31;

    for (int c = t; c < CELLS; c += 256) w[c] = -1;
    if (t == 0) s_cnt = 0;
    const float2 oi = ((const float2*)obs2)[i];    // broadcast load
    __syncthreads();

    int cnt = 0;
    if (oi.x == oi.x) {                            // ego not NaN (uniform)
        for (int j = t; j < N_AG; j += 256) {      // obs2 is L2-resident (8KB)
            if (j == i) continue;
            float2 oj = ((const float2*)obs2)[j];
            if (oj.x != oj.x) continue;            // neighbor NaN
            float ox = (oj.x - oi.x) * 4.0f + 16.0f;   // exact pow2 scale
            float oy = (oj.y - oi.y) * 4.0f + 16.0f;
            if (ox >= 0.0f && ox < 32.0f && oy >= 0.0f && oy < 32.0f)
                atomicMax(&w[((int)ox) * 32 + (int)oy], j);  // set-sem: max j
        }
        __syncthreads();
        for (int c = t; c < CELLS; c += 256) {
            int j = w[c];
            if (j >= 0) {
                int blk = ((c >> 8) << 2) | ((c & 31) >> 3);   // gi*4+gj
                int p = atomicAdd(&s_cnt, 1);
                se[p] = (j << 11) | (blk << 7);    // row offset into P
            }
        }
        __syncthreads();
        cnt = s_cnt;
    }

    griddep_wait();                                // g_P now visible

    float4 acc = make_float4(0.f, 0.f, 0.f, 0.f);
    for (int e = g; e < cnt; e += 8) {
        float4 v = *(const float4*)(g_P + se[e] + l * 4);
        acc.x += v.x; acc.y += v.y; acc.z += v.z; acc.w += v.w;
    }
    sp[g][l] = acc;
    __syncthreads();

    if (g == 0) {
        float4 s = sp[0][l];
#pragma unroll
        for (int q = 1; q < 8; q++) {
            float4 v = sp[q][l];
            s.x += v.x; s.y += v.y; s.z += v.z; s.w += v.w;
        }
        float4 bv = ((const float4*)b)[l];
        s.x = fmaxf(s.x + bv.x, 0.f);
        s.y = fmaxf(s.y + bv.y, 0.f);
        s.z = fmaxf(s.z + bv.z, 0.f);
        s.w = fmaxf(s.w + bv.w, 0.f);
        ((float4*)(out + i * OUTD))[l] = s;
    }
}

// =============================================================================
extern "C" void kernel_launch(void* const* d_in, const int* in_sizes, int n_in,
                              void* d_out, int out_size) {
    const float* hidden = (const float*)d_in[0];
    const float* obs2   = (const float*)d_in[2];
    const float* W      = (const float*)d_in[3];
    const float* b      = (const float*)d_in[4];
    float*       out    = (float*)d_out;

    cudaFuncSetAttribute(gemm_mma_kernel, cudaFuncAttributeMaxDynamicSharedMemorySize, SMEM_DYN);

    prep_kernel<<<128, 256>>>(W);

    cudaLaunchAttribute attr[1];
    attr[0].id = cudaLaunchAttributeProgrammaticStreamSerialization;
    attr[0].val.programmaticStreamSerializationAllowed = 1;

    cudaLaunchConfig_t cfg = {};
    cfg.gridDim = dim3(N_AG / 128, KDIM / 128);   // (8, 16)
    cfg.blockDim = dim3(256);
    cfg.dynamicSmemBytes = SMEM_DYN;
    cfg.stream = 0;
    cfg.attrs = attr;
    cfg.numAttrs = 1;
    cudaLaunchKernelEx(&cfg, gemm_mma_kernel, hidden);

    cfg.gridDim = dim3(N_AG);
    cfg.dynamicSmemBytes = 0;
    cudaLaunchKernelEx(&cfg, out_kernel, obs2, b, out);
}